// round 10
// baseline (speedup 1.0000x reference)
#include <cuda_runtime.h>
#include <cuda_bf16.h>
#include <cstddef>

#define E_TOT 512
#define Dd    64
#define Hh    256
#define Nn    16
#define Aa    8
#define Tt    128
#define HO    (Nn + Aa * Nn)   // 144 head outputs

#define SF2   0.01f
#define SN2   0.01f
#define NEG_HALF_INV_L2 (-50.0f)   // -0.5 / 0.1^2

// scratch (no allocation allowed -> device globals)
__device__ float g_h1[E_TOT * Hh];     // layer-1 activations
__device__ float g_h2[E_TOT * Hh];     // layer-2 activations
__device__ float g_head[E_TOT * HO];   // [times(16) | anchors(128)] per e

// ---------------------------------------------------------------------------
// Tiled GEMM (R7 exact, proven). BM=16 e-rows, BN cols, 256 threads.
// ---------------------------------------------------------------------------
template<int BN, int KTOT, bool DOTANH, bool SPLITW>
__global__ __launch_bounds__(256)
void gemm_kernel(const float* __restrict__ A,
                 const float* __restrict__ W,    // or Wt when SPLITW
                 const float* __restrict__ Wb,   // Wa when SPLITW
                 const float* __restrict__ bias,    // or bt
                 const float* __restrict__ biasb,   // ba when SPLITW
                 float* __restrict__ C, int OUTC)
{
    constexpr int BM  = 16;
    constexpr int RPT = (BM * BN) / 256;    // rows per thread: 2 (BN=32), 1 (BN=16)
    __shared__ float Ash[64][BM + 2];
    __shared__ float Bsh[64][BN + 1];

    const int tid  = threadIdx.x;
    const int c    = tid % BN;
    const int rg   = tid / BN;
    const int row0 = blockIdx.x * BM;
    const int col0 = blockIdx.y * BN;

    float acc[RPT];
    #pragma unroll
    for (int r = 0; r < RPT; r++) acc[r] = 0.0f;

    for (int k0 = 0; k0 < KTOT; k0 += 64) {
        #pragma unroll
        for (int i = tid; i < BM * 64; i += 256) {
            int r = i >> 6, kk = i & 63;
            Ash[kk][r] = A[(row0 + r) * KTOT + k0 + kk];
        }
        #pragma unroll
        for (int i = tid; i < BN * 64; i += 256) {
            int cc = i >> 6, kk = i & 63;
            int cg = col0 + cc;
            float v;
            if (SPLITW) v = (cg < Nn) ? W[cg * KTOT + k0 + kk]
                                      : Wb[(cg - Nn) * KTOT + k0 + kk];
            else        v = W[cg * KTOT + k0 + kk];
            Bsh[kk][cc] = v;
        }
        __syncthreads();

        #pragma unroll 16
        for (int kk = 0; kk < 64; kk++) {
            float b = Bsh[kk][c];
            #pragma unroll
            for (int r = 0; r < RPT; r++)
                acc[r] += Ash[kk][rg * RPT + r] * b;
        }
        __syncthreads();
    }

    #pragma unroll
    for (int r = 0; r < RPT; r++) {
        int row = row0 + rg * RPT + r;
        int col = col0 + c;
        float bv;
        if (SPLITW) bv = (col < Nn) ? bias[col] : biasb[col - Nn];
        else        bv = bias[col];
        float v = acc[r] + bv;
        if (DOTANH) v = tanhf(v);
        C[row * OUTC + col] = v;
    }
}

// ---------------------------------------------------------------------------
// GP per environment e. 512 blocks, 256 threads, forced 4 blocks/SM.
//   Preamble warp-specialized: warp 0 = K build + Gauss-Jordan (syncwarp only),
//   warps 1-7 = Ks + kssd concurrently. One __syncthreads joins them.
//   U is stride-16 (64B rows): LDS.128-aligned; writes are flat-contiguous,
//   cov-loop reads are warp-uniform broadcasts -> no conflicts either way.
// ---------------------------------------------------------------------------
__global__ __launch_bounds__(256, 4)
void gp_kernel(const float* __restrict__ tq_g,
               float* __restrict__ out_mu,
               float* __restrict__ out_cov)
{
    __shared__ float tq[Tt];
    __shared__ float kssd[Tt];               // Kss[i][j] == kssd[|i-j|]
    __shared__ float tt[Nn];
    __shared__ float ys[Aa][Nn];
    __shared__ float Aug[Nn][2 * Nn + 1];    // [K | I] -> [I | K^-1], pad 33
    __shared__ float St[Nn][Tt + 4];         // Ks transposed: St[n][j], pad 132
    __shared__ float U[Tt][Nn];              // U = Ks @ K^-1, stride 16 (aligned)

    const int e    = blockIdx.x;
    const int tid  = threadIdx.x;
    const int wid  = tid >> 5;
    const int lane = tid & 31;

    if (tid < Tt) {
        tq[tid] = tq_g[tid];
        ys[tid >> 4][tid & 15] = g_head[e * HO + Nn + tid];
    } else if (tid < Tt + Nn) {
        tt[tid - Tt] = g_head[e * HO + (tid - Tt)];
    }
    __syncthreads();

    if (wid == 0) {
        // ---- build [K + sn2 I | I] then Gauss-Jordan with syncwarp only ----
        #pragma unroll
        for (int r = 0; r < 8; r++) {
            int idx = r * 32 + lane;
            int i = idx >> 4, j = idx & 15;
            float d = tt[i] - tt[j];
            float v = SF2 * __expf(NEG_HALF_INV_L2 * d * d);
            if (i == j) v += SN2;
            Aug[i][j] = v;
            Aug[i][Nn + j] = (i == j) ? 1.0f : 0.0f;
        }
        __syncwarp();
        for (int k = 0; k < Nn; k++) {
            float pinv = 1.0f / Aug[k][k];
            float rowk = Aug[k][lane] * pinv;
            Aug[k][lane] = rowk;
            __syncwarp();
            #pragma unroll
            for (int i = 0; i < Nn; i++) {
                if (i != k) {
                    float c = Aug[i][k];     // warp-wide LDS precedes the STS
                    Aug[i][lane] -= c * rowk;
                }
            }
            __syncwarp();
        }
    } else {
        // ---- warps 1..7: Ks transposed + kssd table ----
        for (int idx = tid - 32; idx < Tt * Nn; idx += 224) {
            int j = idx >> 4, n = idx & 15;
            float d = tq[j] - tt[n];
            St[n][j] = SF2 * __expf(NEG_HALF_INV_L2 * d * d);
        }
        if (tid >= 32 && tid < 32 + Tt) {
            int j = tid - 32;
            float d = tq[j] - tq[0];
            kssd[j] = SF2 * __expf(NEG_HALF_INV_L2 * d * d);
        }
    }
    __syncthreads();

    // U[i][n] = sum_m Ks[i][m] * Kinv[m][n]   (writes flat-contiguous)
    for (int idx = tid; idx < Tt * Nn; idx += 256) {
        int i = idx >> 4, n = idx & 15;
        float s = 0.0f;
        #pragma unroll
        for (int m = 0; m < Nn; m++) s += St[m][i] * Aug[m][Nn + n];
        U[i][n] = s;
    }
    __syncthreads();

    // mu[a][i] = sum_n U[i][n] * y[a][n]
    for (int idx = tid; idx < Aa * Tt; idx += 256) {
        int a = idx >> 7, i = idx & 127;
        float s = 0.0f;
        #pragma unroll
        for (int n = 0; n < Nn; n++) s += U[i][n] * ys[a][n];
        out_mu[((size_t)e * Aa + a) * Tt + i] = s;
    }

    // cov[i][j] = kssd[|i-j|] - dot16(U[i], Ks[j]); written 8x (one per anchor)
    const int grp = wid;
    const int j0  = lane * 4;
    for (int step = 0; step < Tt / 8; step++) {
        int i = step * 8 + grp;
        float a0 = 0.f, a1 = 0.f, a2 = 0.f, a3 = 0.f;
        #pragma unroll
        for (int n = 0; n < Nn; n += 4) {
            float4 u4 = *(const float4*)&U[i][n];      // aligned LDS.128 broadcast
            float4 s0 = *(const float4*)&St[n + 0][j0];
            float4 s1 = *(const float4*)&St[n + 1][j0];
            float4 s2 = *(const float4*)&St[n + 2][j0];
            float4 s3 = *(const float4*)&St[n + 3][j0];
            a0 += u4.x * s0.x + u4.y * s1.x + u4.z * s2.x + u4.w * s3.x;
            a1 += u4.x * s0.y + u4.y * s1.y + u4.z * s2.y + u4.w * s3.y;
            a2 += u4.x * s0.z + u4.y * s1.z + u4.z * s2.z + u4.w * s3.z;
            a3 += u4.x * s0.w + u4.y * s1.w + u4.z * s2.w + u4.w * s3.w;
        }
        int d0 = i - j0;       d0 = d0 < 0 ? -d0 : d0;
        int d1 = i - (j0 + 1); d1 = d1 < 0 ? -d1 : d1;
        int d2 = i - (j0 + 2); d2 = d2 < 0 ? -d2 : d2;
        int d3 = i - (j0 + 3); d3 = d3 < 0 ? -d3 : d3;
        float4 v;
        v.x = kssd[d0] - a0;
        v.y = kssd[d1] - a1;
        v.z = kssd[d2] - a2;
        v.w = kssd[d3] - a3;
        size_t base = (((size_t)e * Aa) * Tt + i) * Tt + j0;
        #pragma unroll
        for (int a = 0; a < Aa; a++) {
            *(float4*)&out_cov[base + (size_t)a * Tt * Tt] = v;   // coalesced STG.128
        }
    }
}

// ---------------------------------------------------------------------------
extern "C" void kernel_launch(void* const* d_in, const int* in_sizes, int n_in,
                              void* d_out, int out_size)
{
    const float* x  = (const float*)d_in[0];
    // d_in[1] = a, d_in[2] = da (unused by reference)
    const float* W1 = (const float*)d_in[3];
    const float* b1 = (const float*)d_in[4];
    const float* W2 = (const float*)d_in[5];
    const float* b2 = (const float*)d_in[6];
    const float* Wt = (const float*)d_in[7];
    const float* bt = (const float*)d_in[8];
    const float* Wa = (const float*)d_in[9];
    const float* ba = (const float*)d_in[10];
    const float* tq = (const float*)d_in[11];

    float* out     = (float*)d_out;
    float* out_mu  = out;                                   // E*A*T floats
    float* out_cov = out + (size_t)E_TOT * Aa * Tt;         // E*A*T*T floats

    float* h1 = nullptr; float* h2 = nullptr; float* hd = nullptr;
    cudaGetSymbolAddress((void**)&h1, g_h1);
    cudaGetSymbolAddress((void**)&h2, g_h2);
    cudaGetSymbolAddress((void**)&hd, g_head);

    // layer 1: [512,256] = tanh(x @ W1^T + b1), k=64    -> 256 blocks
    gemm_kernel<32, Dd, true, false>
        <<<dim3(E_TOT / 16, Hh / 32), 256>>>(x, W1, nullptr, b1, nullptr, h1, Hh);
    // layer 2: [512,256] = tanh(h1 @ W2^T + b2), k=256  -> 256 blocks
    gemm_kernel<32, Hh, true, false>
        <<<dim3(E_TOT / 16, Hh / 32), 256>>>(h1, W2, nullptr, b2, nullptr, h2, Hh);
    // heads: [512,144] = h2 @ [Wt;Wa]^T + [bt;ba], k=256 -> 288 blocks
    gemm_kernel<16, Hh, false, true>
        <<<dim3(E_TOT / 16, HO / 16), 256>>>(h2, Wt, Wa, bt, ba, hd, HO);

    gp_kernel<<<E_TOT, 256>>>(tq, out_mu, out_cov);
}

// round 11
// speedup vs baseline: 1.1042x; 1.1042x over previous
#include <cuda_runtime.h>
#include <cuda_bf16.h>
#include <cstddef>

#define E_TOT 512
#define Dd    64
#define Hh    256
#define Nn    16
#define Aa    8
#define Tt    128
#define HO    (Nn + Aa * Nn)   // 144 head outputs

#define SF2   0.01f
#define SN2   0.01f
#define NEG_HALF_INV_L2 (-50.0f)   // -0.5 / 0.1^2

// scratch (no allocation allowed -> device globals)
__device__ float g_h1[E_TOT * Hh];     // layer-1 activations
__device__ float g_h2[E_TOT * Hh];     // layer-2 activations
__device__ float g_head[E_TOT * HO];   // [times(16) | anchors(128)] per e

// ---------------------------------------------------------------------------
// Tiled GEMM (R7 tiling/grid). BM=16 e-rows, BN cols, 256 threads.
// k-loop split into even/odd independent partial accumulators so each output
// has 2x the FFMA chains (hides the 4-cyc FFMA latency at rt 2).
// ---------------------------------------------------------------------------
template<int BN, int KTOT, bool DOTANH, bool SPLITW>
__global__ __launch_bounds__(256)
void gemm_kernel(const float* __restrict__ A,
                 const float* __restrict__ W,    // or Wt when SPLITW
                 const float* __restrict__ Wb,   // Wa when SPLITW
                 const float* __restrict__ bias,    // or bt
                 const float* __restrict__ biasb,   // ba when SPLITW
                 float* __restrict__ C, int OUTC)
{
    constexpr int BM  = 16;
    constexpr int RPT = (BM * BN) / 256;    // rows per thread: 2 (BN=32), 1 (BN=16)
    __shared__ float Ash[64][BM + 2];
    __shared__ float Bsh[64][BN + 1];

    const int tid  = threadIdx.x;
    const int c    = tid % BN;
    const int rg   = tid / BN;
    const int row0 = blockIdx.x * BM;
    const int col0 = blockIdx.y * BN;

    float acc0[RPT], acc1[RPT];             // even-k / odd-k partials
    #pragma unroll
    for (int r = 0; r < RPT; r++) { acc0[r] = 0.0f; acc1[r] = 0.0f; }

    for (int k0 = 0; k0 < KTOT; k0 += 64) {
        #pragma unroll
        for (int i = tid; i < BM * 64; i += 256) {
            int r = i >> 6, kk = i & 63;
            Ash[kk][r] = A[(row0 + r) * KTOT + k0 + kk];
        }
        #pragma unroll
        for (int i = tid; i < BN * 64; i += 256) {
            int cc = i >> 6, kk = i & 63;
            int cg = col0 + cc;
            float v;
            if (SPLITW) v = (cg < Nn) ? W[cg * KTOT + k0 + kk]
                                      : Wb[(cg - Nn) * KTOT + k0 + kk];
            else        v = W[cg * KTOT + k0 + kk];
            Bsh[kk][cc] = v;
        }
        __syncthreads();

        #pragma unroll 16
        for (int kk = 0; kk < 64; kk += 2) {
            float b0 = Bsh[kk + 0][c];
            float b1 = Bsh[kk + 1][c];
            #pragma unroll
            for (int r = 0; r < RPT; r++) {
                acc0[r] += Ash[kk + 0][rg * RPT + r] * b0;
                acc1[r] += Ash[kk + 1][rg * RPT + r] * b1;
            }
        }
        __syncthreads();
    }

    #pragma unroll
    for (int r = 0; r < RPT; r++) {
        int row = row0 + rg * RPT + r;
        int col = col0 + c;
        float bv;
        if (SPLITW) bv = (col < Nn) ? bias[col] : biasb[col - Nn];
        else        bv = bias[col];
        float v = acc0[r] + acc1[r] + bv;
        if (DOTANH) v = tanhf(v);
        C[row * OUTC + col] = v;
    }
}

// ---------------------------------------------------------------------------
// GP per environment e. 512 blocks, 256 threads.  (R1-exact body, proven;
// times/anchors sourced from g_head as in R7's passing run.)
// ---------------------------------------------------------------------------
__global__ __launch_bounds__(256)
void gp_kernel(const float* __restrict__ tq_g,
               float* __restrict__ out_mu,
               float* __restrict__ out_cov)
{
    __shared__ float tq[Tt];
    __shared__ float kssd[Tt];               // Kss[i][j] == kssd[|i-j|]
    __shared__ float tt[Nn];
    __shared__ float ys[Aa][Nn];
    __shared__ float Aug[Nn][2 * Nn + 1];    // [K | I] -> [I | K^-1], pad 33
    __shared__ float colk[Nn];
    __shared__ float St[Nn][Tt + 4];         // Ks transposed: St[n][j], pad 132
    __shared__ float U[Tt][Nn + 1];          // U = Ks @ K^-1, pad 17

    const int e   = blockIdx.x;
    const int tid = threadIdx.x;

    if (tid < Tt) tq[tid] = tq_g[tid];
    if (tid < Nn) tt[tid] = g_head[e * HO + tid];
    if (tid >= 128 && tid < 128 + Aa * Nn) {
        int q = tid - 128;
        ys[q >> 4][q & 15] = g_head[e * HO + Nn + q];
    }
    __syncthreads();

    if (tid < Tt) {
        float d = tq[tid] - tq[0];
        kssd[tid] = SF2 * __expf(NEG_HALF_INV_L2 * d * d);
    }
    // build [K + sn2 I | I]  (exactly 256 entries of K)
    {
        int i = tid >> 4, j = tid & 15;
        float d = tt[i] - tt[j];
        float v = SF2 * __expf(NEG_HALF_INV_L2 * d * d);
        if (i == j) v += SN2;
        Aug[i][j] = v;
        Aug[i][Nn + j] = (i == j) ? 1.0f : 0.0f;
    }
    __syncthreads();

    // Gauss-Jordan (SPD, no pivoting needed, cond(K) <= 17)
    for (int k = 0; k < Nn; k++) {
        float pinv = 1.0f / Aug[k][k];
        __syncthreads();
        if (tid < 32) Aug[k][tid] *= pinv;
        if (tid >= 32 && tid < 48) colk[tid - 32] = Aug[tid - 32][k];
        __syncthreads();
        {
            int idx = tid;            // 512 elements, 256 threads, 2 each
            int i0 = idx >> 5, j0 = idx & 31;
            if (i0 != k) Aug[i0][j0] -= colk[i0] * Aug[k][j0];
            idx += 256;
            int i1 = idx >> 5, j1 = idx & 31;
            if (i1 != k) Aug[i1][j1] -= colk[i1] * Aug[k][j1];
        }
        __syncthreads();
    }

    // Ks transposed: St[n][j] = sf2 * exp(-0.5 (tq[j]-t[n])^2 / l2)
    for (int idx = tid; idx < Tt * Nn; idx += 256) {
        int j = idx >> 4, n = idx & 15;
        float d = tq[j] - tt[n];
        St[n][j] = SF2 * __expf(NEG_HALF_INV_L2 * d * d);
    }
    __syncthreads();

    // U[i][n] = sum_m Ks[i][m] * Kinv[m][n]
    for (int idx = tid; idx < Tt * Nn; idx += 256) {
        int i = idx >> 4, n = idx & 15;
        float s = 0.0f;
        #pragma unroll
        for (int m = 0; m < Nn; m++) s += St[m][i] * Aug[m][Nn + n];
        U[i][n] = s;
    }
    __syncthreads();

    // mu[a][i] = sum_n U[i][n] * y[a][n]
    for (int idx = tid; idx < Aa * Tt; idx += 256) {
        int a = idx >> 7, i = idx & 127;
        float s = 0.0f;
        #pragma unroll
        for (int n = 0; n < Nn; n++) s += U[i][n] * ys[a][n];
        out_mu[((size_t)e * Aa + a) * Tt + i] = s;
    }

    // cov[i][j] = kssd[|i-j|] - dot16(U[i], Ks[j]); written 8x (one per anchor)
    const int lane = tid & 31;
    const int grp  = tid >> 5;
    const int j0   = lane * 4;
    for (int step = 0; step < Tt / 8; step++) {
        int i = step * 8 + grp;
        float u[Nn];
        #pragma unroll
        for (int n = 0; n < Nn; n++) u[n] = U[i][n];   // broadcast LDS
        float a0 = 0.f, a1 = 0.f, a2 = 0.f, a3 = 0.f;
        #pragma unroll
        for (int n = 0; n < Nn; n++) {
            float4 s4 = *(const float4*)&St[n][j0];    // conflict-free LDS.128
            float un = u[n];
            a0 += un * s4.x; a1 += un * s4.y; a2 += un * s4.z; a3 += un * s4.w;
        }
        int d0 = i - j0;       d0 = d0 < 0 ? -d0 : d0;
        int d1 = i - (j0 + 1); d1 = d1 < 0 ? -d1 : d1;
        int d2 = i - (j0 + 2); d2 = d2 < 0 ? -d2 : d2;
        int d3 = i - (j0 + 3); d3 = d3 < 0 ? -d3 : d3;
        float4 v;
        v.x = kssd[d0] - a0;
        v.y = kssd[d1] - a1;
        v.z = kssd[d2] - a2;
        v.w = kssd[d3] - a3;
        size_t base = (((size_t)e * Aa) * Tt + i) * Tt + j0;
        #pragma unroll
        for (int a = 0; a < Aa; a++) {
            *(float4*)&out_cov[base + (size_t)a * Tt * Tt] = v;   // coalesced STG.128
        }
    }
}

// ---------------------------------------------------------------------------
extern "C" void kernel_launch(void* const* d_in, const int* in_sizes, int n_in,
                              void* d_out, int out_size)
{
    const float* x  = (const float*)d_in[0];
    // d_in[1] = a, d_in[2] = da (unused by reference)
    const float* W1 = (const float*)d_in[3];
    const float* b1 = (const float*)d_in[4];
    const float* W2 = (const float*)d_in[5];
    const float* b2 = (const float*)d_in[6];
    const float* Wt = (const float*)d_in[7];
    const float* bt = (const float*)d_in[8];
    const float* Wa = (const float*)d_in[9];
    const float* ba = (const float*)d_in[10];
    const float* tq = (const float*)d_in[11];

    float* out     = (float*)d_out;
    float* out_mu  = out;                                   // E*A*T floats
    float* out_cov = out + (size_t)E_TOT * Aa * Tt;         // E*A*T*T floats

    float* h1 = nullptr; float* h2 = nullptr; float* hd = nullptr;
    cudaGetSymbolAddress((void**)&h1, g_h1);
    cudaGetSymbolAddress((void**)&h2, g_h2);
    cudaGetSymbolAddress((void**)&hd, g_head);

    // layer 1: [512,256] = tanh(x @ W1^T + b1), k=64    -> 256 blocks
    gemm_kernel<32, Dd, true, false>
        <<<dim3(E_TOT / 16, Hh / 32), 256>>>(x, W1, nullptr, b1, nullptr, h1, Hh);
    // layer 2: [512,256] = tanh(h1 @ W2^T + b2), k=256  -> 256 blocks
    gemm_kernel<32, Hh, true, false>
        <<<dim3(E_TOT / 16, Hh / 32), 256>>>(h1, W2, nullptr, b2, nullptr, h2, Hh);
    // heads: [512,144] = h2 @ [Wt;Wa]^T + [bt;ba], k=256 -> 288 blocks
    gemm_kernel<16, Hh, false, true>
        <<<dim3(E_TOT / 16, HO / 16), 256>>>(h2, Wt, Wa, bt, ba, hd, HO);

    gp_kernel<<<E_TOT, 256>>>(tq, out_mu, out_cov);
}

// round 12
// speedup vs baseline: 1.2562x; 1.1376x over previous
#include <cuda_runtime.h>
#include <cuda_bf16.h>
#include <cstddef>

#define E_TOT 512
#define Dd    64
#define Hh    256
#define Nn    16
#define Aa    8
#define Tt    128
#define HO    (Nn + Aa * Nn)   // 144 head outputs

#define SF2   0.01f
#define SN2   0.01f
#define NEG_HALF_INV_L2 (-50.0f)   // -0.5 / 0.1^2

// scratch (no allocation allowed -> device globals)
__device__ float g_h1[E_TOT * Hh];     // layer-1 activations
__device__ float g_h2[E_TOT * Hh];     // layer-2 activations
__device__ float g_head[E_TOT * HO];   // [times(16) | anchors(128)] per e

// ---------------------------------------------------------------------------
// Tiled GEMM (R7 tiling/grid, R11 even/odd accumulators, R12 vector staging).
//   BM=16 e-rows, BN cols, 256 threads. Staging uses LDG.128 (rows are
//   16B-aligned at all (k0,kq) offsets: KTOT in {64,256}).
// ---------------------------------------------------------------------------
template<int BN, int KTOT, bool DOTANH, bool SPLITW>
__global__ __launch_bounds__(256)
void gemm_kernel(const float* __restrict__ A,
                 const float* __restrict__ W,    // or Wt when SPLITW
                 const float* __restrict__ Wb,   // Wa when SPLITW
                 const float* __restrict__ bias,    // or bt
                 const float* __restrict__ biasb,   // ba when SPLITW
                 float* __restrict__ C, int OUTC)
{
    constexpr int BM  = 16;
    constexpr int RPT = (BM * BN) / 256;    // rows per thread: 2 (BN=32), 1 (BN=16)
    __shared__ float Ash[64][BM + 2];
    __shared__ float Bsh[64][BN + 1];

    const int tid  = threadIdx.x;
    const int c    = tid % BN;
    const int rg   = tid / BN;
    const int row0 = blockIdx.x * BM;
    const int col0 = blockIdx.y * BN;

    float acc0[RPT], acc1[RPT];             // even-k / odd-k partials
    #pragma unroll
    for (int r = 0; r < RPT; r++) { acc0[r] = 0.0f; acc1[r] = 0.0f; }

    for (int k0 = 0; k0 < KTOT; k0 += 64) {
        // stage A tile: BM*16 float4 loads (LDG.128), transposed scatter STS
        #pragma unroll
        for (int i = tid; i < BM * 16; i += 256) {
            int r  = i >> 4;
            int kq = (i & 15) << 2;
            float4 v4 = *(const float4*)&A[(row0 + r) * KTOT + k0 + kq];
            Ash[kq + 0][r] = v4.x;
            Ash[kq + 1][r] = v4.y;
            Ash[kq + 2][r] = v4.z;
            Ash[kq + 3][r] = v4.w;
        }
        // stage W tile: BN*16 float4 loads
        #pragma unroll
        for (int i = tid; i < BN * 16; i += 256) {
            int cc = i >> 4;
            int kq = (i & 15) << 2;
            int cg = col0 + cc;
            const float* src;
            if (SPLITW) src = (cg < Nn) ? &W[cg * KTOT + k0 + kq]
                                        : &Wb[(cg - Nn) * KTOT + k0 + kq];
            else        src = &W[cg * KTOT + k0 + kq];
            float4 v4 = *(const float4*)src;
            Bsh[kq + 0][cc] = v4.x;
            Bsh[kq + 1][cc] = v4.y;
            Bsh[kq + 2][cc] = v4.z;
            Bsh[kq + 3][cc] = v4.w;
        }
        __syncthreads();

        #pragma unroll 16
        for (int kk = 0; kk < 64; kk += 2) {
            float b0 = Bsh[kk + 0][c];
            float b1 = Bsh[kk + 1][c];
            #pragma unroll
            for (int r = 0; r < RPT; r++) {
                acc0[r] += Ash[kk + 0][rg * RPT + r] * b0;
                acc1[r] += Ash[kk + 1][rg * RPT + r] * b1;
            }
        }
        __syncthreads();
    }

    #pragma unroll
    for (int r = 0; r < RPT; r++) {
        int row = row0 + rg * RPT + r;
        int col = col0 + c;
        float bv;
        if (SPLITW) bv = (col < Nn) ? bias[col] : biasb[col - Nn];
        else        bv = bias[col];
        float v = acc0[r] + acc1[r] + bv;
        if (DOTANH) v = tanhf(v);
        C[row * OUTC + col] = v;
    }
}

// ---------------------------------------------------------------------------
// GP per environment e. 512 blocks, 256 threads.  (R11 body; only change:
// streaming stores for cov/mu -- zero-reuse output, keep L2 for the pipeline.)
// ---------------------------------------------------------------------------
__global__ __launch_bounds__(256)
void gp_kernel(const float* __restrict__ tq_g,
               float* __restrict__ out_mu,
               float* __restrict__ out_cov)
{
    __shared__ float tq[Tt];
    __shared__ float kssd[Tt];               // Kss[i][j] == kssd[|i-j|]
    __shared__ float tt[Nn];
    __shared__ float ys[Aa][Nn];
    __shared__ float Aug[Nn][2 * Nn + 1];    // [K | I] -> [I | K^-1], pad 33
    __shared__ float colk[Nn];
    __shared__ float St[Nn][Tt + 4];         // Ks transposed: St[n][j], pad 132
    __shared__ float U[Tt][Nn + 1];          // U = Ks @ K^-1, pad 17

    const int e   = blockIdx.x;
    const int tid = threadIdx.x;

    if (tid < Tt) tq[tid] = tq_g[tid];
    if (tid < Nn) tt[tid] = g_head[e * HO + tid];
    if (tid >= 128 && tid < 128 + Aa * Nn) {
        int q = tid - 128;
        ys[q >> 4][q & 15] = g_head[e * HO + Nn + q];
    }
    __syncthreads();

    if (tid < Tt) {
        float d = tq[tid] - tq[0];
        kssd[tid] = SF2 * __expf(NEG_HALF_INV_L2 * d * d);
    }
    // build [K + sn2 I | I]  (exactly 256 entries of K)
    {
        int i = tid >> 4, j = tid & 15;
        float d = tt[i] - tt[j];
        float v = SF2 * __expf(NEG_HALF_INV_L2 * d * d);
        if (i == j) v += SN2;
        Aug[i][j] = v;
        Aug[i][Nn + j] = (i == j) ? 1.0f : 0.0f;
    }
    __syncthreads();

    // Gauss-Jordan (SPD, no pivoting needed, cond(K) <= 17)
    for (int k = 0; k < Nn; k++) {
        float pinv = 1.0f / Aug[k][k];
        __syncthreads();
        if (tid < 32) Aug[k][tid] *= pinv;
        if (tid >= 32 && tid < 48) colk[tid - 32] = Aug[tid - 32][k];
        __syncthreads();
        {
            int idx = tid;            // 512 elements, 256 threads, 2 each
            int i0 = idx >> 5, j0 = idx & 31;
            if (i0 != k) Aug[i0][j0] -= colk[i0] * Aug[k][j0];
            idx += 256;
            int i1 = idx >> 5, j1 = idx & 31;
            if (i1 != k) Aug[i1][j1] -= colk[i1] * Aug[k][j1];
        }
        __syncthreads();
    }

    // Ks transposed: St[n][j] = sf2 * exp(-0.5 (tq[j]-t[n])^2 / l2)
    for (int idx = tid; idx < Tt * Nn; idx += 256) {
        int j = idx >> 4, n = idx & 15;
        float d = tq[j] - tt[n];
        St[n][j] = SF2 * __expf(NEG_HALF_INV_L2 * d * d);
    }
    __syncthreads();

    // U[i][n] = sum_m Ks[i][m] * Kinv[m][n]
    for (int idx = tid; idx < Tt * Nn; idx += 256) {
        int i = idx >> 4, n = idx & 15;
        float s = 0.0f;
        #pragma unroll
        for (int m = 0; m < Nn; m++) s += St[m][i] * Aug[m][Nn + n];
        U[i][n] = s;
    }
    __syncthreads();

    // mu[a][i] = sum_n U[i][n] * y[a][n]
    for (int idx = tid; idx < Aa * Tt; idx += 256) {
        int a = idx >> 7, i = idx & 127;
        float s = 0.0f;
        #pragma unroll
        for (int n = 0; n < Nn; n++) s += U[i][n] * ys[a][n];
        __stcs(&out_mu[((size_t)e * Aa + a) * Tt + i], s);
    }

    // cov[i][j] = kssd[|i-j|] - dot16(U[i], Ks[j]); written 8x (one per anchor)
    const int lane = tid & 31;
    const int grp  = tid >> 5;
    const int j0   = lane * 4;
    for (int step = 0; step < Tt / 8; step++) {
        int i = step * 8 + grp;
        float u[Nn];
        #pragma unroll
        for (int n = 0; n < Nn; n++) u[n] = U[i][n];   // broadcast LDS
        float a0 = 0.f, a1 = 0.f, a2 = 0.f, a3 = 0.f;
        #pragma unroll
        for (int n = 0; n < Nn; n++) {
            float4 s4 = *(const float4*)&St[n][j0];    // conflict-free LDS.128
            float un = u[n];
            a0 += un * s4.x; a1 += un * s4.y; a2 += un * s4.z; a3 += un * s4.w;
        }
        int d0 = i - j0;       d0 = d0 < 0 ? -d0 : d0;
        int d1 = i - (j0 + 1); d1 = d1 < 0 ? -d1 : d1;
        int d2 = i - (j0 + 2); d2 = d2 < 0 ? -d2 : d2;
        int d3 = i - (j0 + 3); d3 = d3 < 0 ? -d3 : d3;
        float4 v;
        v.x = kssd[d0] - a0;
        v.y = kssd[d1] - a1;
        v.z = kssd[d2] - a2;
        v.w = kssd[d3] - a3;
        size_t base = (((size_t)e * Aa) * Tt + i) * Tt + j0;
        #pragma unroll
        for (int a = 0; a < Aa; a++) {
            __stcs((float4*)&out_cov[base + (size_t)a * Tt * Tt], v);  // streaming STG.128
        }
    }
}

// ---------------------------------------------------------------------------
extern "C" void kernel_launch(void* const* d_in, const int* in_sizes, int n_in,
                              void* d_out, int out_size)
{
    const float* x  = (const float*)d_in[0];
    // d_in[1] = a, d_in[2] = da (unused by reference)
    const float* W1 = (const float*)d_in[3];
    const float* b1 = (const float*)d_in[4];
    const float* W2 = (const float*)d_in[5];
    const float* b2 = (const float*)d_in[6];
    const float* Wt = (const float*)d_in[7];
    const float* bt = (const float*)d_in[8];
    const float* Wa = (const float*)d_in[9];
    const float* ba = (const float*)d_in[10];
    const float* tq = (const float*)d_in[11];

    float* out     = (float*)d_out;
    float* out_mu  = out;                                   // E*A*T floats
    float* out_cov = out + (size_t)E_TOT * Aa * Tt;         // E*A*T*T floats

    float* h1 = nullptr; float* h2 = nullptr; float* hd = nullptr;
    cudaGetSymbolAddress((void**)&h1, g_h1);
    cudaGetSymbolAddress((void**)&h2, g_h2);
    cudaGetSymbolAddress((void**)&hd, g_head);

    // layer 1: [512,256] = tanh(x @ W1^T + b1), k=64    -> 256 blocks
    gemm_kernel<32, Dd, true, false>
        <<<dim3(E_TOT / 16, Hh / 32), 256>>>(x, W1, nullptr, b1, nullptr, h1, Hh);
    // layer 2: [512,256] = tanh(h1 @ W2^T + b2), k=256  -> 256 blocks
    gemm_kernel<32, Hh, true, false>
        <<<dim3(E_TOT / 16, Hh / 32), 256>>>(h1, W2, nullptr, b2, nullptr, h2, Hh);
    // heads: [512,144] = h2 @ [Wt;Wa]^T + [bt;ba], k=256 -> 288 blocks
    gemm_kernel<16, Hh, false, true>
        <<<dim3(E_TOT / 16, HO / 16), 256>>>(h2, Wt, Wa, bt, ba, hd, HO);

    gp_kernel<<<E_TOT, 256>>>(tq, out_mu, out_cov);
}

// round 13
// speedup vs baseline: 1.3323x; 1.0606x over previous
#include <cuda_runtime.h>
#include <cuda_bf16.h>
#include <cstddef>

#define E_TOT 512
#define Dd    64
#define Hh    256
#define Nn    16
#define Aa    8
#define Tt    128
#define HO    (Nn + Aa * Nn)   // 144 head outputs
#define USTR  20               // U row stride: 80B = 5x16B, float4-aligned

#define SF2   0.01f
#define SN2   0.01f
#define NEG_HALF_INV_L2 (-50.0f)   // -0.5 / 0.1^2

// scratch (no allocation allowed -> device globals)
__device__ float g_h1[E_TOT * Hh];     // layer-1 activations
__device__ float g_h2[E_TOT * Hh];     // layer-2 activations
__device__ float g_head[E_TOT * HO];   // [times(16) | anchors(128)] per e

// ---------------------------------------------------------------------------
// Tiled GEMM (R12 exact, proven). BM=16 e-rows, BN cols, 256 threads,
// LDG.128 staging, even/odd accumulator chains.
// ---------------------------------------------------------------------------
template<int BN, int KTOT, bool DOTANH, bool SPLITW>
__global__ __launch_bounds__(256)
void gemm_kernel(const float* __restrict__ A,
                 const float* __restrict__ W,    // or Wt when SPLITW
                 const float* __restrict__ Wb,   // Wa when SPLITW
                 const float* __restrict__ bias,    // or bt
                 const float* __restrict__ biasb,   // ba when SPLITW
                 float* __restrict__ C, int OUTC)
{
    constexpr int BM  = 16;
    constexpr int RPT = (BM * BN) / 256;    // rows per thread: 2 (BN=32), 1 (BN=16)
    __shared__ float Ash[64][BM + 2];
    __shared__ float Bsh[64][BN + 1];

    const int tid  = threadIdx.x;
    const int c    = tid % BN;
    const int rg   = tid / BN;
    const int row0 = blockIdx.x * BM;
    const int col0 = blockIdx.y * BN;

    float acc0[RPT], acc1[RPT];             // even-k / odd-k partials
    #pragma unroll
    for (int r = 0; r < RPT; r++) { acc0[r] = 0.0f; acc1[r] = 0.0f; }

    for (int k0 = 0; k0 < KTOT; k0 += 64) {
        #pragma unroll
        for (int i = tid; i < BM * 16; i += 256) {
            int r  = i >> 4;
            int kq = (i & 15) << 2;
            float4 v4 = *(const float4*)&A[(row0 + r) * KTOT + k0 + kq];
            Ash[kq + 0][r] = v4.x;
            Ash[kq + 1][r] = v4.y;
            Ash[kq + 2][r] = v4.z;
            Ash[kq + 3][r] = v4.w;
        }
        #pragma unroll
        for (int i = tid; i < BN * 16; i += 256) {
            int cc = i >> 4;
            int kq = (i & 15) << 2;
            int cg = col0 + cc;
            const float* src;
            if (SPLITW) src = (cg < Nn) ? &W[cg * KTOT + k0 + kq]
                                        : &Wb[(cg - Nn) * KTOT + k0 + kq];
            else        src = &W[cg * KTOT + k0 + kq];
            float4 v4 = *(const float4*)src;
            Bsh[kq + 0][cc] = v4.x;
            Bsh[kq + 1][cc] = v4.y;
            Bsh[kq + 2][cc] = v4.z;
            Bsh[kq + 3][cc] = v4.w;
        }
        __syncthreads();

        #pragma unroll 16
        for (int kk = 0; kk < 64; kk += 2) {
            float b0 = Bsh[kk + 0][c];
            float b1 = Bsh[kk + 1][c];
            #pragma unroll
            for (int r = 0; r < RPT; r++) {
                acc0[r] += Ash[kk + 0][rg * RPT + r] * b0;
                acc1[r] += Ash[kk + 1][rg * RPT + r] * b1;
            }
        }
        __syncthreads();
    }

    #pragma unroll
    for (int r = 0; r < RPT; r++) {
        int row = row0 + rg * RPT + r;
        int col = col0 + c;
        float bv;
        if (SPLITW) bv = (col < Nn) ? bias[col] : biasb[col - Nn];
        else        bv = bias[col];
        float v = acc0[r] + acc1[r] + bv;
        if (DOTANH) v = tanhf(v);
        C[row * OUTC + col] = v;
    }
}

// ---------------------------------------------------------------------------
// GP per environment e. 512 blocks, 256 threads. R12 body with the cov-loop
// L1-wavefront diet: St[0..7] register-cached, U re-strided to 20 floats so
// u reads are 4 aligned LDS.128 broadcasts (and mu reads are conflict-free).
// ---------------------------------------------------------------------------
__global__ __launch_bounds__(256)
void gp_kernel(const float* __restrict__ tq_g,
               float* __restrict__ out_mu,
               float* __restrict__ out_cov)
{
    __shared__ float tq[Tt];
    __shared__ float kssd[Tt];                        // Kss[i][j] == kssd[|i-j|]
    __shared__ float tt[Nn];
    __shared__ float ys[Aa][Nn];
    __shared__ float Aug[Nn][2 * Nn + 1];             // [K | I] -> [I | K^-1]
    __shared__ float colk[Nn];
    __shared__ __align__(16) float St[Nn][Tt + 4];    // Ks^T, pad 132 (16B mult)
    __shared__ __align__(16) float U[Tt][USTR];       // U = Ks K^-1, stride 20

    const int e   = blockIdx.x;
    const int tid = threadIdx.x;

    if (tid < Tt) tq[tid] = tq_g[tid];
    if (tid < Nn) tt[tid] = g_head[e * HO + tid];
    if (tid >= 128 && tid < 128 + Aa * Nn) {
        int q = tid - 128;
        ys[q >> 4][q & 15] = g_head[e * HO + Nn + q];
    }
    __syncthreads();

    if (tid < Tt) {
        float d = tq[tid] - tq[0];
        kssd[tid] = SF2 * __expf(NEG_HALF_INV_L2 * d * d);
    }
    // build [K + sn2 I | I]
    {
        int i = tid >> 4, j = tid & 15;
        float d = tt[i] - tt[j];
        float v = SF2 * __expf(NEG_HALF_INV_L2 * d * d);
        if (i == j) v += SN2;
        Aug[i][j] = v;
        Aug[i][Nn + j] = (i == j) ? 1.0f : 0.0f;
    }
    __syncthreads();

    // Gauss-Jordan (SPD, no pivoting needed, cond(K) <= 17)
    for (int k = 0; k < Nn; k++) {
        float pinv = 1.0f / Aug[k][k];
        __syncthreads();
        if (tid < 32) Aug[k][tid] *= pinv;
        if (tid >= 32 && tid < 48) colk[tid - 32] = Aug[tid - 32][k];
        __syncthreads();
        {
            int idx = tid;
            int i0 = idx >> 5, j0 = idx & 31;
            if (i0 != k) Aug[i0][j0] -= colk[i0] * Aug[k][j0];
            idx += 256;
            int i1 = idx >> 5, j1 = idx & 31;
            if (i1 != k) Aug[i1][j1] -= colk[i1] * Aug[k][j1];
        }
        __syncthreads();
    }

    // Ks transposed: St[n][j] = sf2 * exp(-0.5 (tq[j]-t[n])^2 / l2)
    for (int idx = tid; idx < Tt * Nn; idx += 256) {
        int j = idx >> 4, n = idx & 15;
        float d = tq[j] - tt[n];
        St[n][j] = SF2 * __expf(NEG_HALF_INV_L2 * d * d);
    }
    __syncthreads();

    // U[i][n] = sum_m Ks[i][m] * Kinv[m][n]
    for (int idx = tid; idx < Tt * Nn; idx += 256) {
        int i = idx >> 4, n = idx & 15;
        float s = 0.0f;
        #pragma unroll
        for (int m = 0; m < Nn; m++) s += St[m][i] * Aug[m][Nn + n];
        U[i][n] = s;
    }
    __syncthreads();

    // mu[a][i] = dot16(U[i], y[a])   (U rows are 4 aligned float4s)
    for (int idx = tid; idx < Aa * Tt; idx += 256) {
        int a = idx >> 7, i = idx & 127;
        float4 u0 = *(const float4*)&U[i][0];
        float4 u1 = *(const float4*)&U[i][4];
        float4 u2 = *(const float4*)&U[i][8];
        float4 u3 = *(const float4*)&U[i][12];
        float s = u0.x * ys[a][0]  + u0.y * ys[a][1]  + u0.z * ys[a][2]  + u0.w * ys[a][3]
                + u1.x * ys[a][4]  + u1.y * ys[a][5]  + u1.z * ys[a][6]  + u1.w * ys[a][7]
                + u2.x * ys[a][8]  + u2.y * ys[a][9]  + u2.z * ys[a][10] + u2.w * ys[a][11]
                + u3.x * ys[a][12] + u3.y * ys[a][13] + u3.z * ys[a][14] + u3.w * ys[a][15];
        __stcs(&out_mu[((size_t)e * Aa + a) * Tt + i], s);
    }

    // cov[i][j] = kssd[|i-j|] - dot16(U[i], Ks[j]); written 8x streaming
    const int lane = tid & 31;
    const int grp  = tid >> 5;
    const int j0   = lane * 4;
    float4 s8[8];                                     // St[0..7][j0..3] cached
    #pragma unroll
    for (int n = 0; n < 8; n++) s8[n] = *(const float4*)&St[n][j0];

    for (int step = 0; step < Tt / 8; step++) {
        int i = step * 8 + grp;
        float4 u0 = *(const float4*)&U[i][0];          // broadcast LDS.128 x4
        float4 u1 = *(const float4*)&U[i][4];
        float4 u2 = *(const float4*)&U[i][8];
        float4 u3 = *(const float4*)&U[i][12];

        float a0 = u0.x * s8[0].x + u0.y * s8[1].x + u0.z * s8[2].x + u0.w * s8[3].x
                 + u1.x * s8[4].x + u1.y * s8[5].x + u1.z * s8[6].x + u1.w * s8[7].x;
        float a1 = u0.x * s8[0].y + u0.y * s8[1].y + u0.z * s8[2].y + u0.w * s8[3].y
                 + u1.x * s8[4].y + u1.y * s8[5].y + u1.z * s8[6].y + u1.w * s8[7].y;
        float a2 = u0.x * s8[0].z + u0.y * s8[1].z + u0.z * s8[2].z + u0.w * s8[3].z
                 + u1.x * s8[4].z + u1.y * s8[5].z + u1.z * s8[6].z + u1.w * s8[7].z;
        float a3 = u0.x * s8[0].w + u0.y * s8[1].w + u0.z * s8[2].w + u0.w * s8[3].w
                 + u1.x * s8[4].w + u1.y * s8[5].w + u1.z * s8[6].w + u1.w * s8[7].w;

        #pragma unroll
        for (int n = 8; n < 16; n++) {
            float4 s4 = *(const float4*)&St[n][j0];    // conflict-free LDS.128
            float un = (n < 12) ? ((n == 8) ? u2.x : (n == 9) ? u2.y : (n == 10) ? u2.z : u2.w)
                                : ((n == 12) ? u3.x : (n == 13) ? u3.y : (n == 14) ? u3.z : u3.w);
            a0 += un * s4.x; a1 += un * s4.y; a2 += un * s4.z; a3 += un * s4.w;
        }

        int d0 = i - j0;       d0 = d0 < 0 ? -d0 : d0;
        int d1 = i - (j0 + 1); d1 = d1 < 0 ? -d1 : d1;
        int d2 = i - (j0 + 2); d2 = d2 < 0 ? -d2 : d2;
        int d3 = i - (j0 + 3); d3 = d3 < 0 ? -d3 : d3;
        float4 v;
        v.x = kssd[d0] - a0;
        v.y = kssd[d1] - a1;
        v.z = kssd[d2] - a2;
        v.w = kssd[d3] - a3;
        size_t base = (((size_t)e * Aa) * Tt + i) * Tt + j0;
        #pragma unroll
        for (int a = 0; a < Aa; a++) {
            __stcs((float4*)&out_cov[base + (size_t)a * Tt * Tt], v);  // streaming STG.128
        }
    }
}

// ---------------------------------------------------------------------------
extern "C" void kernel_launch(void* const* d_in, const int* in_sizes, int n_in,
                              void* d_out, int out_size)
{
    const float* x  = (const float*)d_in[0];
    // d_in[1] = a, d_in[2] = da (unused by reference)
    const float* W1 = (const float*)d_in[3];
    const float* b1 = (const float*)d_in[4];
    const float* W2 = (const float*)d_in[5];
    const float* b2 = (const float*)d_in[6];
    const float* Wt = (const float*)d_in[7];
    const float* bt = (const float*)d_in[8];
    const float* Wa = (const float*)d_in[9];
    const float* ba = (const float*)d_in[10];
    const float* tq = (const float*)d_in[11];

    float* out     = (float*)d_out;
    float* out_mu  = out;                                   // E*A*T floats
    float* out_cov = out + (size_t)E_TOT * Aa * Tt;         // E*A*T*T floats

    float* h1 = nullptr; float* h2 = nullptr; float* hd = nullptr;
    cudaGetSymbolAddress((void**)&h1, g_h1);
    cudaGetSymbolAddress((void**)&h2, g_h2);
    cudaGetSymbolAddress((void**)&hd, g_head);

    // layer 1: [512,256] = tanh(x @ W1^T + b1), k=64    -> 256 blocks
    gemm_kernel<32, Dd, true, false>
        <<<dim3(E_TOT / 16, Hh / 32), 256>>>(x, W1, nullptr, b1, nullptr, h1, Hh);
    // layer 2: [512,256] = tanh(h1 @ W2^T + b2), k=256  -> 256 blocks
    gemm_kernel<32, Hh, true, false>
        <<<dim3(E_TOT / 16, Hh / 32), 256>>>(h1, W2, nullptr, b2, nullptr, h2, Hh);
    // heads: [512,144] = h2 @ [Wt;Wa]^T + [bt;ba], k=256 -> 288 blocks
    gemm_kernel<16, Hh, false, true>
        <<<dim3(E_TOT / 16, HO / 16), 256>>>(h2, Wt, Wa, bt, ba, hd, HO);

    gp_kernel<<<E_TOT, 256>>>(tq, out_mu, out_cov);
}

// round 14
// speedup vs baseline: 1.3648x; 1.0244x over previous
#include <cuda_runtime.h>
#include <cuda_bf16.h>
#include <cstddef>

#define E_TOT 512
#define Dd    64
#define Hh    256
#define Nn    16
#define Aa    8
#define Tt    128
#define HO    (Nn + Aa * Nn)   // 144 head outputs
#define USTR  20               // U row stride: 80B = 5x16B, float4-aligned

#define SF2   0.01f
#define SN2   0.01f
#define NEG_HALF_INV_L2 (-50.0f)   // -0.5 / 0.1^2

// scratch (no allocation allowed -> device globals)
__device__ float g_h1[E_TOT * Hh];     // layer-1 activations
__device__ float g_h2[E_TOT * Hh];     // layer-2 activations
__device__ float g_head[E_TOT * HO];   // [times(16) | anchors(128)] per e

// ---------------------------------------------------------------------------
// Tiled GEMM, row-major smem tiles (stride 68 floats = 17x16B: every
// &T[r][4k] is 16B-aligned). Staging is LDG.128 -> STS.128; inner loop is
// k-step-4: 1 LDS.128 (B) + RPT broadcast LDS.128 (A) + 4*RPT FFMA into
// 4 independent chains per output row.
// ---------------------------------------------------------------------------
template<int BN, int KTOT, bool DOTANH, bool SPLITW>
__global__ __launch_bounds__(256)
void gemm_kernel(const float* __restrict__ A,
                 const float* __restrict__ W,    // or Wt when SPLITW
                 const float* __restrict__ Wb,   // Wa when SPLITW
                 const float* __restrict__ bias,    // or bt
                 const float* __restrict__ biasb,   // ba when SPLITW
                 float* __restrict__ C, int OUTC)
{
    constexpr int BM  = 16;
    constexpr int RPT = (BM * BN) / 256;    // rows per thread: 2 (BN=32), 1 (BN=16)
    __shared__ __align__(16) float Ash[BM][68];
    __shared__ __align__(16) float Bsh[BN][68];

    const int tid  = threadIdx.x;
    const int c    = tid % BN;
    const int rg   = tid / BN;
    const int row0 = blockIdx.x * BM;
    const int col0 = blockIdx.y * BN;

    float acc[RPT][4];
    #pragma unroll
    for (int r = 0; r < RPT; r++)
        #pragma unroll
        for (int q = 0; q < 4; q++) acc[r][q] = 0.0f;

    for (int k0 = 0; k0 < KTOT; k0 += 64) {
        // stage A tile: BM*16 float4s, LDG.128 -> STS.128
        #pragma unroll
        for (int i = tid; i < BM * 16; i += 256) {
            int r  = i >> 4;
            int kq = (i & 15) << 2;
            *(float4*)&Ash[r][kq] = *(const float4*)&A[(row0 + r) * KTOT + k0 + kq];
        }
        // stage W tile: BN*16 float4s
        #pragma unroll
        for (int i = tid; i < BN * 16; i += 256) {
            int cc = i >> 4;
            int kq = (i & 15) << 2;
            int cg = col0 + cc;
            const float* src;
            if (SPLITW) src = (cg < Nn) ? &W[cg * KTOT + k0 + kq]
                                        : &Wb[(cg - Nn) * KTOT + k0 + kq];
            else        src = &W[cg * KTOT + k0 + kq];
            *(float4*)&Bsh[cc][kq] = *(const float4*)src;
        }
        __syncthreads();

        #pragma unroll
        for (int kk = 0; kk < 64; kk += 4) {
            float4 b4 = *(const float4*)&Bsh[c][kk];       // LDS.128, dedup'd
            #pragma unroll
            for (int r = 0; r < RPT; r++) {
                float4 a4 = *(const float4*)&Ash[rg * RPT + r][kk];  // broadcast
                acc[r][0] += a4.x * b4.x;
                acc[r][1] += a4.y * b4.y;
                acc[r][2] += a4.z * b4.z;
                acc[r][3] += a4.w * b4.w;
            }
        }
        __syncthreads();
    }

    #pragma unroll
    for (int r = 0; r < RPT; r++) {
        int row = row0 + rg * RPT + r;
        int col = col0 + c;
        float bv;
        if (SPLITW) bv = (col < Nn) ? bias[col] : biasb[col - Nn];
        else        bv = bias[col];
        float v = (acc[r][0] + acc[r][1]) + (acc[r][2] + acc[r][3]) + bv;
        if (DOTANH) v = tanhf(v);
        C[row * OUTC + col] = v;
    }
}

// ---------------------------------------------------------------------------
// GP per environment e. 512 blocks, 256 threads.  (R13 body, byte-frozen:
// proven 50.4us -- St[0..7] register cache, U stride 20, streaming stores.)
// ---------------------------------------------------------------------------
__global__ __launch_bounds__(256)
void gp_kernel(const float* __restrict__ tq_g,
               float* __restrict__ out_mu,
               float* __restrict__ out_cov)
{
    __shared__ float tq[Tt];
    __shared__ float kssd[Tt];                        // Kss[i][j] == kssd[|i-j|]
    __shared__ float tt[Nn];
    __shared__ float ys[Aa][Nn];
    __shared__ float Aug[Nn][2 * Nn + 1];             // [K | I] -> [I | K^-1]
    __shared__ float colk[Nn];
    __shared__ __align__(16) float St[Nn][Tt + 4];    // Ks^T, pad 132 (16B mult)
    __shared__ __align__(16) float U[Tt][USTR];       // U = Ks K^-1, stride 20

    const int e   = blockIdx.x;
    const int tid = threadIdx.x;

    if (tid < Tt) tq[tid] = tq_g[tid];
    if (tid < Nn) tt[tid] = g_head[e * HO + tid];
    if (tid >= 128 && tid < 128 + Aa * Nn) {
        int q = tid - 128;
        ys[q >> 4][q & 15] = g_head[e * HO + Nn + q];
    }
    __syncthreads();

    if (tid < Tt) {
        float d = tq[tid] - tq[0];
        kssd[tid] = SF2 * __expf(NEG_HALF_INV_L2 * d * d);
    }
    // build [K + sn2 I | I]
    {
        int i = tid >> 4, j = tid & 15;
        float d = tt[i] - tt[j];
        float v = SF2 * __expf(NEG_HALF_INV_L2 * d * d);
        if (i == j) v += SN2;
        Aug[i][j] = v;
        Aug[i][Nn + j] = (i == j) ? 1.0f : 0.0f;
    }
    __syncthreads();

    // Gauss-Jordan (SPD, no pivoting needed, cond(K) <= 17)
    for (int k = 0; k < Nn; k++) {
        float pinv = 1.0f / Aug[k][k];
        __syncthreads();
        if (tid < 32) Aug[k][tid] *= pinv;
        if (tid >= 32 && tid < 48) colk[tid - 32] = Aug[tid - 32][k];
        __syncthreads();
        {
            int idx = tid;
            int i0 = idx >> 5, j0 = idx & 31;
            if (i0 != k) Aug[i0][j0] -= colk[i0] * Aug[k][j0];
            idx += 256;
            int i1 = idx >> 5, j1 = idx & 31;
            if (i1 != k) Aug[i1][j1] -= colk[i1] * Aug[k][j1];
        }
        __syncthreads();
    }

    // Ks transposed: St[n][j] = sf2 * exp(-0.5 (tq[j]-t[n])^2 / l2)
    for (int idx = tid; idx < Tt * Nn; idx += 256) {
        int j = idx >> 4, n = idx & 15;
        float d = tq[j] - tt[n];
        St[n][j] = SF2 * __expf(NEG_HALF_INV_L2 * d * d);
    }
    __syncthreads();

    // U[i][n] = sum_m Ks[i][m] * Kinv[m][n]
    for (int idx = tid; idx < Tt * Nn; idx += 256) {
        int i = idx >> 4, n = idx & 15;
        float s = 0.0f;
        #pragma unroll
        for (int m = 0; m < Nn; m++) s += St[m][i] * Aug[m][Nn + n];
        U[i][n] = s;
    }
    __syncthreads();

    // mu[a][i] = dot16(U[i], y[a])   (U rows are 4 aligned float4s)
    for (int idx = tid; idx < Aa * Tt; idx += 256) {
        int a = idx >> 7, i = idx & 127;
        float4 u0 = *(const float4*)&U[i][0];
        float4 u1 = *(const float4*)&U[i][4];
        float4 u2 = *(const float4*)&U[i][8];
        float4 u3 = *(const float4*)&U[i][12];
        float s = u0.x * ys[a][0]  + u0.y * ys[a][1]  + u0.z * ys[a][2]  + u0.w * ys[a][3]
                + u1.x * ys[a][4]  + u1.y * ys[a][5]  + u1.z * ys[a][6]  + u1.w * ys[a][7]
                + u2.x * ys[a][8]  + u2.y * ys[a][9]  + u2.z * ys[a][10] + u2.w * ys[a][11]
                + u3.x * ys[a][12] + u3.y * ys[a][13] + u3.z * ys[a][14] + u3.w * ys[a][15];
        __stcs(&out_mu[((size_t)e * Aa + a) * Tt + i], s);
    }

    // cov[i][j] = kssd[|i-j|] - dot16(U[i], Ks[j]); written 8x streaming
    const int lane = tid & 31;
    const int grp  = tid >> 5;
    const int j0   = lane * 4;
    float4 s8[8];                                     // St[0..7][j0..3] cached
    #pragma unroll
    for (int n = 0; n < 8; n++) s8[n] = *(const float4*)&St[n][j0];

    for (int step = 0; step < Tt / 8; step++) {
        int i = step * 8 + grp;
        float4 u0 = *(const float4*)&U[i][0];          // broadcast LDS.128 x4
        float4 u1 = *(const float4*)&U[i][4];
        float4 u2 = *(const float4*)&U[i][8];
        float4 u3 = *(const float4*)&U[i][12];

        float a0 = u0.x * s8[0].x + u0.y * s8[1].x + u0.z * s8[2].x + u0.w * s8[3].x
                 + u1.x * s8[4].x + u1.y * s8[5].x + u1.z * s8[6].x + u1.w * s8[7].x;
        float a1 = u0.x * s8[0].y + u0.y * s8[1].y + u0.z * s8[2].y + u0.w * s8[3].y
                 + u1.x * s8[4].y + u1.y * s8[5].y + u1.z * s8[6].y + u1.w * s8[7].y;
        float a2 = u0.x * s8[0].z + u0.y * s8[1].z + u0.z * s8[2].z + u0.w * s8[3].z
                 + u1.x * s8[4].z + u1.y * s8[5].z + u1.z * s8[6].z + u1.w * s8[7].z;
        float a3 = u0.x * s8[0].w + u0.y * s8[1].w + u0.z * s8[2].w + u0.w * s8[3].w
                 + u1.x * s8[4].w + u1.y * s8[5].w + u1.z * s8[6].w + u1.w * s8[7].w;

        #pragma unroll
        for (int n = 8; n < 16; n++) {
            float4 s4 = *(const float4*)&St[n][j0];    // conflict-free LDS.128
            float un = (n < 12) ? ((n == 8) ? u2.x : (n == 9) ? u2.y : (n == 10) ? u2.z : u2.w)
                                : ((n == 12) ? u3.x : (n == 13) ? u3.y : (n == 14) ? u3.z : u3.w);
            a0 += un * s4.x; a1 += un * s4.y; a2 += un * s4.z; a3 += un * s4.w;
        }

        int d0 = i - j0;       d0 = d0 < 0 ? -d0 : d0;
        int d1 = i - (j0 + 1); d1 = d1 < 0 ? -d1 : d1;
        int d2 = i - (j0 + 2); d2 = d2 < 0 ? -d2 : d2;
        int d3 = i - (j0 + 3); d3 = d3 < 0 ? -d3 : d3;
        float4 v;
        v.x = kssd[d0] - a0;
        v.y = kssd[d1] - a1;
        v.z = kssd[d2] - a2;
        v.w = kssd[d3] - a3;
        size_t base = (((size_t)e * Aa) * Tt + i) * Tt + j0;
        #pragma unroll
        for (int a = 0; a < Aa; a++) {
            __stcs((float4*)&out_cov[base + (size_t)a * Tt * Tt], v);  // streaming STG.128
        }
    }
}

// ---------------------------------------------------------------------------
extern "C" void kernel_launch(void* const* d_in, const int* in_sizes, int n_in,
                              void* d_out, int out_size)
{
    const float* x  = (const float*)d_in[0];
    // d_in[1] = a, d_in[2] = da (unused by reference)
    const float* W1 = (const float*)d_in[3];
    const float* b1 = (const float*)d_in[4];
    const float* W2 = (const float*)d_in[5];
    const float* b2 = (const float*)d_in[6];
    const float* Wt = (const float*)d_in[7];
    const float* bt = (const float*)d_in[8];
    const float* Wa = (const float*)d_in[9];
    const float* ba = (const float*)d_in[10];
    const float* tq = (const float*)d_in[11];

    float* out     = (float*)d_out;
    float* out_mu  = out;                                   // E*A*T floats
    float* out_cov = out + (size_t)E_TOT * Aa * Tt;         // E*A*T*T floats

    float* h1 = nullptr; float* h2 = nullptr; float* hd = nullptr;
    cudaGetSymbolAddress((void**)&h1, g_h1);
    cudaGetSymbolAddress((void**)&h2, g_h2);
    cudaGetSymbolAddress((void**)&hd, g_head);

    // layer 1: [512,256] = tanh(x @ W1^T + b1), k=64    -> 256 blocks
    gemm_kernel<32, Dd, true, false>
        <<<dim3(E_TOT / 16, Hh / 32), 256>>>(x, W1, nullptr, b1, nullptr, h1, Hh);
    // layer 2: [512,256] = tanh(h1 @ W2^T + b2), k=256  -> 256 blocks
    gemm_kernel<32, Hh, true, false>
        <<<dim3(E_TOT / 16, Hh / 32), 256>>>(h1, W2, nullptr, b2, nullptr, h2, Hh);
    // heads: [512,144] = h2 @ [Wt;Wa]^T + [bt;ba], k=256 -> 288 blocks
    gemm_kernel<16, Hh, false, true>
        <<<dim3(E_TOT / 16, HO / 16), 256>>>(h2, Wt, Wa, bt, ba, hd, HO);

    gp_kernel<<<E_TOT, 256>>>(tq, out_mu, out_cov);
}

// round 15
// speedup vs baseline: 1.3910x; 1.0192x over previous
#include <cuda_runtime.h>
#include <cuda_bf16.h>
#include <cstddef>

#define E_TOT 512
#define Dd    64
#define Hh    256
#define Nn    16
#define Aa    8
#define Tt    128
#define HO    (Nn + Aa * Nn)   // 144 head outputs
#define USTR  20               // U row stride: 80B = 5x16B, float4-aligned

#define SF2   0.01f
#define SN2   0.01f
#define NEG_HALF_INV_L2 (-50.0f)   // -0.5 / 0.1^2

// scratch (no allocation allowed -> device globals)
__device__ float g_h1[E_TOT * Hh];     // layer-1 activations
__device__ float g_h2[E_TOT * Hh];     // layer-2 activations
__device__ float g_head[E_TOT * HO];   // [times(16) | anchors(128)] per e

// ---------------------------------------------------------------------------
// Tiled GEMM, row-major smem tiles (stride 68 = 17x16B), LDG.128->STS.128
// staging with REGISTER-PREFETCH double buffering: next tile's LDGs issue
// before the inner loop so global latency overlaps compute.
// ---------------------------------------------------------------------------
template<int BN, int KTOT, bool DOTANH, bool SPLITW>
__global__ __launch_bounds__(256)
void gemm_kernel(const float* __restrict__ A,
                 const float* __restrict__ W,    // or Wt when SPLITW
                 const float* __restrict__ Wb,   // Wa when SPLITW
                 const float* __restrict__ bias,    // or bt
                 const float* __restrict__ biasb,   // ba when SPLITW
                 float* __restrict__ C, int OUTC)
{
    constexpr int BM  = 16;
    constexpr int RPT = (BM * BN) / 256;    // rows per thread: 2 (BN=32), 1 (BN=16)
    constexpr int NA  = (BM * 16) / 256;    // A float4s per thread (1)
    constexpr int NW  = (BN * 16) / 256;    // W float4s per thread (2 or 1)
    __shared__ __align__(16) float Ash[BM][68];
    __shared__ __align__(16) float Bsh[BN][68];

    const int tid  = threadIdx.x;
    const int c    = tid % BN;
    const int rg   = tid / BN;
    const int row0 = blockIdx.x * BM;
    const int col0 = blockIdx.y * BN;

    float acc[RPT][4];
    #pragma unroll
    for (int r = 0; r < RPT; r++)
        #pragma unroll
        for (int q = 0; q < 4; q++) acc[r][q] = 0.0f;

    float4 pa[NA], pw[NW];
    // prefetch tile 0
    #pragma unroll
    for (int u = 0; u < NA; u++) {
        int i = tid + u * 256;
        int r = i >> 4, kq = (i & 15) << 2;
        pa[u] = *(const float4*)&A[(row0 + r) * KTOT + kq];
    }
    #pragma unroll
    for (int u = 0; u < NW; u++) {
        int i = tid + u * 256;
        int cc = i >> 4, kq = (i & 15) << 2;
        int cg = col0 + cc;
        const float* src;
        if (SPLITW) src = (cg < Nn) ? &W[cg * KTOT + kq]
                                    : &Wb[(cg - Nn) * KTOT + kq];
        else        src = &W[cg * KTOT + kq];
        pw[u] = *(const float4*)src;
    }

    for (int k0 = 0; k0 < KTOT; k0 += 64) {
        // commit prefetched tile to smem
        #pragma unroll
        for (int u = 0; u < NA; u++) {
            int i = tid + u * 256;
            int r = i >> 4, kq = (i & 15) << 2;
            *(float4*)&Ash[r][kq] = pa[u];
        }
        #pragma unroll
        for (int u = 0; u < NW; u++) {
            int i = tid + u * 256;
            int cc = i >> 4, kq = (i & 15) << 2;
            *(float4*)&Bsh[cc][kq] = pw[u];
        }
        __syncthreads();

        // prefetch next tile (LDG latency overlaps the inner loop)
        if (k0 + 64 < KTOT) {
            int kn = k0 + 64;
            #pragma unroll
            for (int u = 0; u < NA; u++) {
                int i = tid + u * 256;
                int r = i >> 4, kq = (i & 15) << 2;
                pa[u] = *(const float4*)&A[(row0 + r) * KTOT + kn + kq];
            }
            #pragma unroll
            for (int u = 0; u < NW; u++) {
                int i = tid + u * 256;
                int cc = i >> 4, kq = (i & 15) << 2;
                int cg = col0 + cc;
                const float* src;
                if (SPLITW) src = (cg < Nn) ? &W[cg * KTOT + kn + kq]
                                            : &Wb[(cg - Nn) * KTOT + kn + kq];
                else        src = &W[cg * KTOT + kn + kq];
                pw[u] = *(const float4*)src;
            }
        }

        #pragma unroll
        for (int kk = 0; kk < 64; kk += 4) {
            float4 b4 = *(const float4*)&Bsh[c][kk];       // LDS.128, dedup'd
            #pragma unroll
            for (int r = 0; r < RPT; r++) {
                float4 a4 = *(const float4*)&Ash[rg * RPT + r][kk];  // broadcast
                acc[r][0] += a4.x * b4.x;
                acc[r][1] += a4.y * b4.y;
                acc[r][2] += a4.z * b4.z;
                acc[r][3] += a4.w * b4.w;
            }
        }
        __syncthreads();
    }

    #pragma unroll
    for (int r = 0; r < RPT; r++) {
        int row = row0 + rg * RPT + r;
        int col = col0 + c;
        float bv;
        if (SPLITW) bv = (col < Nn) ? bias[col] : biasb[col - Nn];
        else        bv = bias[col];
        float v = (acc[r][0] + acc[r][1]) + (acc[r][2] + acc[r][3]) + bv;
        if (DOTANH) v = tanhf(v);
        C[row * OUTC + col] = v;
    }
}

// ---------------------------------------------------------------------------
// GP per environment e. 512 blocks, 256 threads. R13 body + FULL St register
// cache in the cov loop (s16): cov-loop LDS wavefronts ~halved again.
// ---------------------------------------------------------------------------
__global__ __launch_bounds__(256)
void gp_kernel(const float* __restrict__ tq_g,
               float* __restrict__ out_mu,
               float* __restrict__ out_cov)
{
    __shared__ float tq[Tt];
    __shared__ float kssd[Tt];                        // Kss[i][j] == kssd[|i-j|]
    __shared__ float tt[Nn];
    __shared__ float ys[Aa][Nn];
    __shared__ float Aug[Nn][2 * Nn + 1];             // [K | I] -> [I | K^-1]
    __shared__ float colk[Nn];
    __shared__ __align__(16) float St[Nn][Tt + 4];    // Ks^T, pad 132 (16B mult)
    __shared__ __align__(16) float U[Tt][USTR];       // U = Ks K^-1, stride 20

    const int e   = blockIdx.x;
    const int tid = threadIdx.x;

    if (tid < Tt) tq[tid] = tq_g[tid];
    if (tid < Nn) tt[tid] = g_head[e * HO + tid];
    if (tid >= 128 && tid < 128 + Aa * Nn) {
        int q = tid - 128;
        ys[q >> 4][q & 15] = g_head[e * HO + Nn + q];
    }
    __syncthreads();

    if (tid < Tt) {
        float d = tq[tid] - tq[0];
        kssd[tid] = SF2 * __expf(NEG_HALF_INV_L2 * d * d);
    }
    // build [K + sn2 I | I]
    {
        int i = tid >> 4, j = tid & 15;
        float d = tt[i] - tt[j];
        float v = SF2 * __expf(NEG_HALF_INV_L2 * d * d);
        if (i == j) v += SN2;
        Aug[i][j] = v;
        Aug[i][Nn + j] = (i == j) ? 1.0f : 0.0f;
    }
    __syncthreads();

    // Gauss-Jordan (SPD, no pivoting needed, cond(K) <= 17)
    for (int k = 0; k < Nn; k++) {
        float pinv = 1.0f / Aug[k][k];
        __syncthreads();
        if (tid < 32) Aug[k][tid] *= pinv;
        if (tid >= 32 && tid < 48) colk[tid - 32] = Aug[tid - 32][k];
        __syncthreads();
        {
            int idx = tid;
            int i0 = idx >> 5, j0 = idx & 31;
            if (i0 != k) Aug[i0][j0] -= colk[i0] * Aug[k][j0];
            idx += 256;
            int i1 = idx >> 5, j1 = idx & 31;
            if (i1 != k) Aug[i1][j1] -= colk[i1] * Aug[k][j1];
        }
        __syncthreads();
    }

    // Ks transposed: St[n][j] = sf2 * exp(-0.5 (tq[j]-t[n])^2 / l2)
    for (int idx = tid; idx < Tt * Nn; idx += 256) {
        int j = idx >> 4, n = idx & 15;
        float d = tq[j] - tt[n];
        St[n][j] = SF2 * __expf(NEG_HALF_INV_L2 * d * d);
    }
    __syncthreads();

    // U[i][n] = sum_m Ks[i][m] * Kinv[m][n]
    for (int idx = tid; idx < Tt * Nn; idx += 256) {
        int i = idx >> 4, n = idx & 15;
        float s = 0.0f;
        #pragma unroll
        for (int m = 0; m < Nn; m++) s += St[m][i] * Aug[m][Nn + n];
        U[i][n] = s;
    }
    __syncthreads();

    // mu[a][i] = dot16(U[i], y[a])   (U rows are 4 aligned float4s)
    for (int idx = tid; idx < Aa * Tt; idx += 256) {
        int a = idx >> 7, i = idx & 127;
        float4 u0 = *(const float4*)&U[i][0];
        float4 u1 = *(const float4*)&U[i][4];
        float4 u2 = *(const float4*)&U[i][8];
        float4 u3 = *(const float4*)&U[i][12];
        float s = u0.x * ys[a][0]  + u0.y * ys[a][1]  + u0.z * ys[a][2]  + u0.w * ys[a][3]
                + u1.x * ys[a][4]  + u1.y * ys[a][5]  + u1.z * ys[a][6]  + u1.w * ys[a][7]
                + u2.x * ys[a][8]  + u2.y * ys[a][9]  + u2.z * ys[a][10] + u2.w * ys[a][11]
                + u3.x * ys[a][12] + u3.y * ys[a][13] + u3.z * ys[a][14] + u3.w * ys[a][15];
        __stcs(&out_mu[((size_t)e * Aa + a) * Tt + i], s);
    }

    // cov[i][j] = kssd[|i-j|] - dot16(U[i], Ks[j]); written 8x streaming
    const int lane = tid & 31;
    const int grp  = tid >> 5;
    const int j0   = lane * 4;
    float4 s16[16];                                   // full St[:, j0..j0+3] cache
    #pragma unroll
    for (int n = 0; n < 16; n++) s16[n] = *(const float4*)&St[n][j0];

    for (int step = 0; step < Tt / 8; step++) {
        int i = step * 8 + grp;
        float4 u0 = *(const float4*)&U[i][0];          // broadcast LDS.128 x4
        float4 u1 = *(const float4*)&U[i][4];
        float4 u2 = *(const float4*)&U[i][8];
        float4 u3 = *(const float4*)&U[i][12];

        float a0 = u0.x * s16[0].x + u0.y * s16[1].x + u0.z * s16[2].x + u0.w * s16[3].x
                 + u1.x * s16[4].x + u1.y * s16[5].x + u1.z * s16[6].x + u1.w * s16[7].x
                 + u2.x * s16[8].x + u2.y * s16[9].x + u2.z * s16[10].x + u2.w * s16[11].x
                 + u3.x * s16[12].x + u3.y * s16[13].x + u3.z * s16[14].x + u3.w * s16[15].x;
        float a1 = u0.x * s16[0].y + u0.y * s16[1].y + u0.z * s16[2].y + u0.w * s16[3].y
                 + u1.x * s16[4].y + u1.y * s16[5].y + u1.z * s16[6].y + u1.w * s16[7].y
                 + u2.x * s16[8].y + u2.y * s16[9].y + u2.z * s16[10].y + u2.w * s16[11].y
                 + u3.x * s16[12].y + u3.y * s16[13].y + u3.z * s16[14].y + u3.w * s16[15].y;
        float a2 = u0.x * s16[0].z + u0.y * s16[1].z + u0.z * s16[2].z + u0.w * s16[3].z
                 + u1.x * s16[4].z + u1.y * s16[5].z + u1.z * s16[6].z + u1.w * s16[7].z
                 + u2.x * s16[8].z + u2.y * s16[9].z + u2.z * s16[10].z + u2.w * s16[11].z
                 + u3.x * s16[12].z + u3.y * s16[13].z + u3.z * s16[14].z + u3.w * s16[15].z;
        float a3 = u0.x * s16[0].w + u0.y * s16[1].w + u0.z * s16[2].w + u0.w * s16[3].w
                 + u1.x * s16[4].w + u1.y * s16[5].w + u1.z * s16[6].w + u1.w * s16[7].w
                 + u2.x * s16[8].w + u2.y * s16[9].w + u2.z * s16[10].w + u2.w * s16[11].w
                 + u3.x * s16[12].w + u3.y * s16[13].w + u3.z * s16[14].w + u3.w * s16[15].w;

        int d0 = i - j0;       d0 = d0 < 0 ? -d0 : d0;
        int d1 = i - (j0 + 1); d1 = d1 < 0 ? -d1 : d1;
        int d2 = i - (j0 + 2); d2 = d2 < 0 ? -d2 : d2;
        int d3 = i - (j0 + 3); d3 = d3 < 0 ? -d3 : d3;
        float4 v;
        v.x = kssd[d0] - a0;
        v.y = kssd[d1] - a1;
        v.z = kssd[d2] - a2;
        v.w = kssd[d3] - a3;
        size_t base = (((size_t)e * Aa) * Tt + i) * Tt + j0;
        #pragma unroll
        for (int a = 0; a < Aa; a++) {
            __stcs((float4*)&out_cov[base + (size_t)a * Tt * Tt], v);  // streaming STG.128
        }
    }
}

// ---------------------------------------------------------------------------
extern "C" void kernel_launch(void* const* d_in, const int* in_sizes, int n_in,
                              void* d_out, int out_size)
{
    const float* x  = (const float*)d_in[0];
    // d_in[1] = a, d_in[2] = da (unused by reference)
    const float* W1 = (const float*)d_in[3];
    const float* b1 = (const float*)d_in[4];
    const float* W2 = (const float*)d_in[5];
    const float* b2 = (const float*)d_in[6];
    const float* Wt = (const float*)d_in[7];
    const float* bt = (const float*)d_in[8];
    const float* Wa = (const float*)d_in[9];
    const float* ba = (const float*)d_in[10];
    const float* tq = (const float*)d_in[11];

    float* out     = (float*)d_out;
    float* out_mu  = out;                                   // E*A*T floats
    float* out_cov = out + (size_t)E_TOT * Aa * Tt;         // E*A*T*T floats

    float* h1 = nullptr; float* h2 = nullptr; float* hd = nullptr;
    cudaGetSymbolAddress((void**)&h1, g_h1);
    cudaGetSymbolAddress((void**)&h2, g_h2);
    cudaGetSymbolAddress((void**)&hd, g_head);

    // layer 1: [512,256] = tanh(x @ W1^T + b1), k=64    -> 256 blocks
    gemm_kernel<32, Dd, true, false>
        <<<dim3(E_TOT / 16, Hh / 32), 256>>>(x, W1, nullptr, b1, nullptr, h1, Hh);
    // layer 2: [512,256] = tanh(h1 @ W2^T + b2), k=256  -> 256 blocks
    gemm_kernel<32, Hh, true, false>
        <<<dim3(E_TOT / 16, Hh / 32), 256>>>(h1, W2, nullptr, b2, nullptr, h2, Hh);
    // heads: [512,144] = h2 @ [Wt;Wa]^T + [bt;ba], k=256 -> 288 blocks
    gemm_kernel<16, Hh, false, true>
        <<<dim3(E_TOT / 16, HO / 16), 256>>>(h2, Wt, Wa, bt, ba, hd, HO);

    gp_kernel<<<E_TOT, 256>>>(tq, out_mu, out_cov);
}